// round 1
// baseline (speedup 1.0000x reference)
#include <cuda_runtime.h>

#define Lq 128
#define Bq 128
#define Dq 1024
#define Aq 1024
#define Hq 2048

// Scratch (device globals: allocation-free, graph-safe)
__device__ float g_proj[Bq * Aq];     // (B, A)
__device__ float g_scores[Lq * Bq];   // (L, B)

__device__ __forceinline__ float tanh_fast(float x) {
    float y;
    asm("tanh.approx.f32 %0, %1;" : "=f"(y) : "f"(x));
    return y;
}

// ---------------------------------------------------------------------------
// K1: proj[b][a] = dot(s_tm1[b,:], W_sa[a,:]) + b_sa[a]
// 32(b) x 32(a) tile per block, BK=32, 256 threads, 4 outputs/thread.
// Grid: (A/32, B/32) = (32, 4) = 128 blocks (one full wave).
// ---------------------------------------------------------------------------
__global__ void __launch_bounds__(256) k_proj(const float* __restrict__ S,
                                              const float* __restrict__ W,
                                              const float* __restrict__ bsa) {
    const int a0 = blockIdx.x * 32;
    const int b0 = blockIdx.y * 32;
    __shared__ float Ss[32][36];  // [m][k], padded: float4-aligned, conflict-free
    __shared__ float Ws[32][36];  // [k][n], transposed store, conflict-free

    const int t  = threadIdx.x;
    const int lr = t >> 3;         // 0..31 : row loaded by this thread
    const int lc = (t & 7) << 2;   // 0..28 : k-offset (float4)
    const int m  = t >> 3;         // output row (b-local)
    const int n0 = (t & 7) << 2;   // output col group (a-local)

    float c0 = 0.f, c1 = 0.f, c2 = 0.f, c3 = 0.f;

    for (int k0 = 0; k0 < Dq; k0 += 32) {
        float4 sv = *(const float4*)(S + (size_t)(b0 + lr) * Dq + k0 + lc);
        float4 wv = *(const float4*)(W + (size_t)(a0 + lr) * Dq + k0 + lc);
        __syncthreads();
        *(float4*)&Ss[lr][lc] = sv;
        Ws[lc + 0][lr] = wv.x;
        Ws[lc + 1][lr] = wv.y;
        Ws[lc + 2][lr] = wv.z;
        Ws[lc + 3][lr] = wv.w;
        __syncthreads();
#pragma unroll
        for (int k = 0; k < 32; ++k) {
            float a = Ss[m][k];
            float4 b4 = *(const float4*)&Ws[k][n0];
            c0 = fmaf(a, b4.x, c0);
            c1 = fmaf(a, b4.y, c1);
            c2 = fmaf(a, b4.z, c2);
            c3 = fmaf(a, b4.w, c3);
        }
    }
    float4 bias = *(const float4*)(bsa + a0 + n0);
    float4 r;
    r.x = c0 + bias.x;
    r.y = c1 + bias.y;
    r.z = c2 + bias.z;
    r.w = c3 + bias.w;
    *(float4*)(g_proj + (size_t)(b0 + m) * Aq + a0 + n0) = r;
}

// ---------------------------------------------------------------------------
// K2: score[l,b] = sum_a w_a1[a] * tanh(proj[b,a] + uh[l,b,a])
// One warp per (l,b). Block = 8 warps sharing one b (proj + w_a1 in smem).
// Grid: B * L/8 = 2048 blocks, 256 threads.
// ---------------------------------------------------------------------------
__global__ void __launch_bounds__(256) k_scores(const float* __restrict__ uh,
                                                const float* __restrict__ w1) {
    const int b  = blockIdx.x >> 4;
    const int l0 = (blockIdx.x & 15) << 3;
    __shared__ float ps[Aq];
    __shared__ float ws[Aq];
    const int t = threadIdx.x;

    *(float4*)&ps[t * 4] = *(const float4*)(g_proj + (size_t)b * Aq + t * 4);
    *(float4*)&ws[t * 4] = *(const float4*)(w1 + t * 4);
    __syncthreads();

    const int w    = t >> 5;
    const int lane = t & 31;
    const int l    = l0 + w;
    const float* u = uh + (size_t)(l * Bq + b) * Aq;

    float acc = 0.f;
#pragma unroll
    for (int i = 0; i < 8; ++i) {
        int idx = i * 128 + lane * 4;
        float4 u4 = *(const float4*)(u + idx);
        float4 p4 = *(const float4*)&ps[idx];
        float4 w4 = *(const float4*)&ws[idx];
        acc = fmaf(w4.x, tanh_fast(p4.x + u4.x), acc);
        acc = fmaf(w4.y, tanh_fast(p4.y + u4.y), acc);
        acc = fmaf(w4.z, tanh_fast(p4.z + u4.z), acc);
        acc = fmaf(w4.w, tanh_fast(p4.w + u4.w), acc);
    }
#pragma unroll
    for (int off = 16; off; off >>= 1)
        acc += __shfl_xor_sync(0xffffffffu, acc, off);
    if (lane == 0) g_scores[l * Bq + b] = acc;
}

// ---------------------------------------------------------------------------
// K3: e[l,b] = exp(score + b_a1) * mask;  e /= sum_l e  -> d_out (e_ij part)
// Block per b (128 blocks), 128 threads (one per l).
// ---------------------------------------------------------------------------
__global__ void __launch_bounds__(128) k_softmax(const float* __restrict__ mask,
                                                 const float* __restrict__ ba1,
                                                 float* __restrict__ e_out) {
    const int b = blockIdx.x;
    const int l = threadIdx.x;
    float e = __expf(g_scores[l * Bq + b] + ba1[0]) * mask[l * Bq + b];

    float v = e;
#pragma unroll
    for (int off = 16; off; off >>= 1)
        v += __shfl_xor_sync(0xffffffffu, v, off);
    __shared__ float part[4];
    if ((l & 31) == 0) part[l >> 5] = v;
    __syncthreads();
    float s = part[0] + part[1] + part[2] + part[3];
    e_out[l * Bq + b] = e / s;
}

// ---------------------------------------------------------------------------
// K4: attend[b,h] = sum_l e[l,b] * xs_h[l,b,h]
// Block per (b, 512-wide h chunk): grid 512, 128 threads, float4 per thread.
// ---------------------------------------------------------------------------
__global__ void __launch_bounds__(128) k_attend(const float* __restrict__ xs,
                                                const float* __restrict__ e,
                                                float* __restrict__ out) {
    const int b  = blockIdx.x >> 2;
    const int h0 = (blockIdx.x & 3) * 512;
    const int t  = threadIdx.x;

    __shared__ float es[Lq];
    es[t] = e[t * Bq + b];
    __syncthreads();

    float4 acc = make_float4(0.f, 0.f, 0.f, 0.f);
    const float* base = xs + (size_t)b * Hq + h0 + t * 4;
#pragma unroll 4
    for (int l = 0; l < Lq; ++l) {
        float4 v = *(const float4*)(base + (size_t)l * Bq * Hq);
        float ev = es[l];
        acc.x = fmaf(ev, v.x, acc.x);
        acc.y = fmaf(ev, v.y, acc.y);
        acc.z = fmaf(ev, v.z, acc.z);
        acc.w = fmaf(ev, v.w, acc.w);
    }
    *(float4*)(out + (size_t)b * Hq + h0 + t * 4) = acc;
}

// ---------------------------------------------------------------------------
extern "C" void kernel_launch(void* const* d_in, const int* in_sizes, int n_in,
                              void* d_out, int out_size) {
    const float* s_tm1 = (const float*)d_in[0];
    const float* xs_h  = (const float*)d_in[1];
    const float* uh    = (const float*)d_in[2];
    const float* mask  = (const float*)d_in[3];
    const float* W_sa  = (const float*)d_in[4];
    const float* b_sa  = (const float*)d_in[5];
    const float* w_a1  = (const float*)d_in[6];
    const float* b_a1  = (const float*)d_in[7];
    float* out = (float*)d_out;           // [0 : L*B) = e_ij, [L*B : ) = attend

    k_proj<<<dim3(32, 4), 256>>>(s_tm1, W_sa, b_sa);
    k_scores<<<2048, 256>>>(uh, w_a1);
    k_softmax<<<128, 128>>>(mask, b_a1, out);
    k_attend<<<512, 128>>>(xs_h, out, out + Lq * Bq);
}

// round 2
// speedup vs baseline: 1.0936x; 1.0936x over previous
#include <cuda_runtime.h>

#define Lq 128
#define Bq 128
#define Dq 1024
#define Aq 1024
#define Hq 2048
#define KSPLIT 4

// Scratch (device globals: allocation-free, graph-safe)
__device__ float g_projp[KSPLIT * Bq * Aq];  // split-K partials (ks, B, A)
__device__ float g_scores[Lq * Bq];          // (L, B)

__device__ __forceinline__ float tanh_fast(float x) {
    float y;
    asm("tanh.approx.f32 %0, %1;" : "=f"(y) : "f"(x));
    return y;
}

__device__ __forceinline__ unsigned long long pack2(float x, float y) {
    unsigned long long r;
    asm("mov.b64 %0, {%1, %2};" : "=l"(r) : "f"(x), "f"(y));
    return r;
}
__device__ __forceinline__ unsigned long long ffma2(unsigned long long a,
                                                    unsigned long long b,
                                                    unsigned long long c) {
    unsigned long long d;
    asm("fma.rn.f32x2 %0, %1, %2, %3;" : "=l"(d) : "l"(a), "l"(b), "l"(c));
    return d;
}

// ---------------------------------------------------------------------------
// K1: proj partials. Tile 32(b) x 64(a), BK=32, split-K=4 (K-range 256/block).
// 256 threads, 8 outputs/thread via f32x2 packed FMA.
// Grid: (A/64, B/32, KSPLIT) = (16, 4, 4) = 256 blocks.
// ---------------------------------------------------------------------------
__global__ void __launch_bounds__(256) k_proj(const float* __restrict__ S,
                                              const float* __restrict__ W) {
    const int a0    = blockIdx.x * 64;
    const int b0    = blockIdx.y * 32;
    const int kbase = blockIdx.z * (Dq / KSPLIT);

    __shared__ float Ss[32][36];   // [b][k], padded (144B row: 16B-aligned, b'cast-safe)
    __shared__ float Ws[32][68];   // [k][a], padded (272B row: 16B-aligned)

    const int t  = threadIdx.x;
    const int lr = t >> 3;          // 0..31
    const int lc = (t & 7) << 2;    // 0,4,...,28 (k-offset for loads)
    const int m  = t >> 3;          // output b-row
    const int n0 = (t & 7) << 3;    // output a-col group (8 wide)

    unsigned long long c0 = 0ull, c1 = 0ull, c2 = 0ull, c3 = 0ull;

    for (int k0 = kbase; k0 < kbase + Dq / KSPLIT; k0 += 32) {
        float4 sv  = *(const float4*)(S + (size_t)(b0 + lr) * Dq + k0 + lc);
        float4 wv0 = *(const float4*)(W + (size_t)(a0 + lr) * Dq + k0 + lc);
        float4 wv1 = *(const float4*)(W + (size_t)(a0 + lr + 32) * Dq + k0 + lc);
        __syncthreads();
        *(float4*)&Ss[lr][lc] = sv;
        Ws[lc + 0][lr] = wv0.x;  Ws[lc + 1][lr] = wv0.y;
        Ws[lc + 2][lr] = wv0.z;  Ws[lc + 3][lr] = wv0.w;
        Ws[lc + 0][lr + 32] = wv1.x;  Ws[lc + 1][lr + 32] = wv1.y;
        Ws[lc + 2][lr + 32] = wv1.z;  Ws[lc + 3][lr + 32] = wv1.w;
        __syncthreads();
#pragma unroll
        for (int k = 0; k < 32; ++k) {
            float a = Ss[m][k];
            unsigned long long aa = pack2(a, a);
            ulonglong2 w0 = *(const ulonglong2*)&Ws[k][n0];
            ulonglong2 w1 = *(const ulonglong2*)&Ws[k][n0 + 4];
            c0 = ffma2(aa, w0.x, c0);
            c1 = ffma2(aa, w0.y, c1);
            c2 = ffma2(aa, w1.x, c2);
            c3 = ffma2(aa, w1.y, c3);
        }
    }
    float* dst = g_projp + ((size_t)blockIdx.z * Bq + b0 + m) * Aq + a0 + n0;
    ulonglong2 r0; r0.x = c0; r0.y = c1;
    ulonglong2 r1; r1.x = c2; r1.y = c3;
    *(ulonglong2*)dst       = r0;
    *(ulonglong2*)(dst + 4) = r1;
}

// ---------------------------------------------------------------------------
// K2: score[l,b] = sum_a w_a1[a] * tanh(proj[b,a] + uh[l,b,a])
// Stages proj = sum of KSPLIT partials + bias into smem (partials are
// L2-resident: 2MB). One warp per (l,b); 8 warps share one b.
// Grid: B * L/8 = 2048 blocks, 256 threads.
// ---------------------------------------------------------------------------
__global__ void __launch_bounds__(256) k_scores(const float* __restrict__ uh,
                                                const float* __restrict__ w1,
                                                const float* __restrict__ bsa) {
    const int b  = blockIdx.x >> 4;
    const int l0 = (blockIdx.x & 15) << 3;
    __shared__ float ps[Aq];
    __shared__ float ws[Aq];
    const int t  = threadIdx.x;
    const int i4 = t * 4;

    float4 p0 = *(const float4*)(g_projp + ((size_t)0 * Bq + b) * Aq + i4);
    float4 p1 = *(const float4*)(g_projp + ((size_t)1 * Bq + b) * Aq + i4);
    float4 p2 = *(const float4*)(g_projp + ((size_t)2 * Bq + b) * Aq + i4);
    float4 p3 = *(const float4*)(g_projp + ((size_t)3 * Bq + b) * Aq + i4);
    float4 bi = *(const float4*)(bsa + i4);
    float4 pv;
    pv.x = (p0.x + p1.x) + (p2.x + p3.x) + bi.x;
    pv.y = (p0.y + p1.y) + (p2.y + p3.y) + bi.y;
    pv.z = (p0.z + p1.z) + (p2.z + p3.z) + bi.z;
    pv.w = (p0.w + p1.w) + (p2.w + p3.w) + bi.w;
    *(float4*)&ps[i4] = pv;
    *(float4*)&ws[i4] = *(const float4*)(w1 + i4);
    __syncthreads();

    const int w    = t >> 5;
    const int lane = t & 31;
    const int l    = l0 + w;
    const float* u = uh + (size_t)(l * Bq + b) * Aq;

    float acc = 0.f;
#pragma unroll
    for (int i = 0; i < 8; ++i) {
        int idx = i * 128 + lane * 4;
        float4 u4 = *(const float4*)(u + idx);
        float4 p4 = *(const float4*)&ps[idx];
        float4 w4 = *(const float4*)&ws[idx];
        acc = fmaf(w4.x, tanh_fast(p4.x + u4.x), acc);
        acc = fmaf(w4.y, tanh_fast(p4.y + u4.y), acc);
        acc = fmaf(w4.z, tanh_fast(p4.z + u4.z), acc);
        acc = fmaf(w4.w, tanh_fast(p4.w + u4.w), acc);
    }
#pragma unroll
    for (int off = 16; off; off >>= 1)
        acc += __shfl_xor_sync(0xffffffffu, acc, off);
    if (lane == 0) g_scores[l * Bq + b] = acc;
}

// ---------------------------------------------------------------------------
// K3: fused softmax + attend.
// Block = (b, 512-wide h chunk), 256 threads. Each block recomputes the
// (cheap, deterministic) softmax over L from g_scores, the h0==0 block also
// writes e_ij. L is split across the two 128-thread halves (smem combine)
// to double occupancy vs round-1.
// Grid: B*4 = 512 blocks.
// ---------------------------------------------------------------------------
__global__ void __launch_bounds__(256) k_attend(const float* __restrict__ xs,
                                                const float* __restrict__ mask,
                                                const float* __restrict__ ba1,
                                                float* __restrict__ e_out,
                                                float* __restrict__ out) {
    const int b  = blockIdx.x >> 2;
    const int h0 = (blockIdx.x & 3) * 512;
    const int t  = threadIdx.x;

    __shared__ float  es[Lq];
    __shared__ float  red[8];
    __shared__ float4 pacc[128];

    // softmax over L (threads 0..127 hold one l each; warps 4..7 contribute 0)
    float e = 0.f;
    if (t < 128)
        e = __expf(g_scores[t * Bq + b] + ba1[0]) * mask[t * Bq + b];
    float v = e;
#pragma unroll
    for (int off = 16; off; off >>= 1)
        v += __shfl_xor_sync(0xffffffffu, v, off);
    if ((t & 31) == 0) red[t >> 5] = v;
    __syncthreads();
    float s = red[0] + red[1] + red[2] + red[3];
    if (t < 128) es[t] = e / s;
    __syncthreads();
    if (h0 == 0 && t < 128) e_out[t * Bq + b] = es[t];

    // weighted sum over L (split: thread half lh covers 64 l values)
    const int col = t & 127;
    const int lh  = t >> 7;
    const float* base = xs + (size_t)(lh * 64) * Bq * Hq +
                        (size_t)b * Hq + h0 + col * 4;
    float4 acc = make_float4(0.f, 0.f, 0.f, 0.f);
#pragma unroll 8
    for (int i = 0; i < 64; ++i) {
        float4 vv = *(const float4*)(base + (size_t)i * Bq * Hq);
        float ev = es[lh * 64 + i];
        acc.x = fmaf(ev, vv.x, acc.x);
        acc.y = fmaf(ev, vv.y, acc.y);
        acc.z = fmaf(ev, vv.z, acc.z);
        acc.w = fmaf(ev, vv.w, acc.w);
    }
    if (lh == 1) pacc[col] = acc;
    __syncthreads();
    if (lh == 0) {
        float4 o = pacc[col];
        acc.x += o.x;  acc.y += o.y;  acc.z += o.z;  acc.w += o.w;
        *(float4*)(out + (size_t)b * Hq + h0 + col * 4) = acc;
    }
}

// ---------------------------------------------------------------------------
extern "C" void kernel_launch(void* const* d_in, const int* in_sizes, int n_in,
                              void* d_out, int out_size) {
    const float* s_tm1 = (const float*)d_in[0];
    const float* xs_h  = (const float*)d_in[1];
    const float* uh    = (const float*)d_in[2];
    const float* mask  = (const float*)d_in[3];
    const float* W_sa  = (const float*)d_in[4];
    const float* b_sa  = (const float*)d_in[5];
    const float* w_a1  = (const float*)d_in[6];
    const float* b_a1  = (const float*)d_in[7];
    float* out = (float*)d_out;  // [0 : L*B) = e_ij, [L*B : ) = attend

    k_proj<<<dim3(16, 4, KSPLIT), 256>>>(s_tm1, W_sa);
    k_scores<<<2048, 256>>>(uh, w_a1, b_sa);
    k_attend<<<512, 256>>>(xs_h, mask, b_a1, out, out + Lq * Bq);
}

// round 3
// speedup vs baseline: 1.6815x; 1.5375x over previous
#include <cuda_runtime.h>

#define Lq 128
#define Bq 128
#define Dq 1024
#define Aq 1024
#define Hq 2048
#define KSPLIT 8
#define KC (Dq / KSPLIT)   // 128 k per split block

typedef unsigned long long ull;

// Scratch (device globals: allocation-free, graph-safe)
__device__ float g_projp[KSPLIT * Bq * Aq];  // split-K partials
__device__ float g_proj[Bq * Aq];            // reduced proj + bias
__device__ float g_scores[Lq * Bq];          // (L, B)

__device__ __forceinline__ float tanh_fast(float x) {
    float y;
    asm("tanh.approx.f32 %0, %1;" : "=f"(y) : "f"(x));
    return y;
}
__device__ __forceinline__ ull pack2(float x, float y) {
    ull r;
    asm("mov.b64 %0, {%1, %2};" : "=l"(r) : "f"(x), "f"(y));
    return r;
}
__device__ __forceinline__ void unpack2(ull v, float& lo, float& hi) {
    asm("mov.b64 {%0, %1}, %2;" : "=f"(lo), "=f"(hi) : "l"(v));
}
__device__ __forceinline__ ull ffma2(ull a, ull b, ull c) {
    ull d;
    asm("fma.rn.f32x2 %0, %1, %2, %3;" : "=l"(d) : "l"(a), "l"(b), "l"(c));
    return d;
}

// ---------------------------------------------------------------------------
// K1: proj partials. Register-tiled SGEMM: 128(b) x 64(a) tile, KT=16,
// split-K=8. 256 threads; each thread owns an 8(m) x 4(n) register tile
// as f32x2 pairs (a-pairs loaded pre-packed from smem).
// Grid: (A/64, KSPLIT) = (16, 8) = 128 blocks (one wave).
// ---------------------------------------------------------------------------
__global__ void __launch_bounds__(256) k_proj(const float* __restrict__ S,
                                              const float* __restrict__ W) {
    const int a0    = blockIdx.x * 64;
    const int kbase = blockIdx.y * KC;

    __shared__ float As[16][132];  // [k][m], 132*4=528B rows (16B aligned)
    __shared__ float Bs[16][68];   // [k][n], 272B rows (16B aligned)

    const int t  = threadIdx.x;
    const int ar = t >> 1;          // A load row (0..127)
    const int ac = (t & 1) * 8;     // A load col base (0 or 8)
    const int br = t >> 2;          // B load row (0..63)
    const int bc = (t & 3) * 4;     // B load col base
    const int tx = t & 15;          // output n-group (4 wide)
    const int ty = t >> 4;          // output m-group (8 wide)

    ull acc[4][4];
#pragma unroll
    for (int i = 0; i < 4; ++i)
#pragma unroll
        for (int j = 0; j < 4; ++j) acc[i][j] = 0ull;

    for (int kt = 0; kt < KC; kt += 16) {
        const int k0 = kbase + kt;
        float4 av0 = *(const float4*)(S + (size_t)ar * Dq + k0 + ac);
        float4 av1 = *(const float4*)(S + (size_t)ar * Dq + k0 + ac + 4);
        float4 bv  = *(const float4*)(W + (size_t)(a0 + br) * Dq + k0 + bc);
        __syncthreads();
        As[ac + 0][ar] = av0.x;  As[ac + 1][ar] = av0.y;
        As[ac + 2][ar] = av0.z;  As[ac + 3][ar] = av0.w;
        As[ac + 4][ar] = av1.x;  As[ac + 5][ar] = av1.y;
        As[ac + 6][ar] = av1.z;  As[ac + 7][ar] = av1.w;
        Bs[bc + 0][br] = bv.x;   Bs[bc + 1][br] = bv.y;
        Bs[bc + 2][br] = bv.z;   Bs[bc + 3][br] = bv.w;
        __syncthreads();
#pragma unroll
        for (int kk = 0; kk < 16; ++kk) {
            ulonglong2 a01 = *(const ulonglong2*)&As[kk][ty * 8];
            ulonglong2 a23 = *(const ulonglong2*)&As[kk][ty * 8 + 4];
            float4 b = *(const float4*)&Bs[kk][tx * 4];
            ull b0 = pack2(b.x, b.x), b1 = pack2(b.y, b.y);
            ull b2 = pack2(b.z, b.z), b3 = pack2(b.w, b.w);
            acc[0][0] = ffma2(a01.x, b0, acc[0][0]);
            acc[0][1] = ffma2(a01.x, b1, acc[0][1]);
            acc[0][2] = ffma2(a01.x, b2, acc[0][2]);
            acc[0][3] = ffma2(a01.x, b3, acc[0][3]);
            acc[1][0] = ffma2(a01.y, b0, acc[1][0]);
            acc[1][1] = ffma2(a01.y, b1, acc[1][1]);
            acc[1][2] = ffma2(a01.y, b2, acc[1][2]);
            acc[1][3] = ffma2(a01.y, b3, acc[1][3]);
            acc[2][0] = ffma2(a23.x, b0, acc[2][0]);
            acc[2][1] = ffma2(a23.x, b1, acc[2][1]);
            acc[2][2] = ffma2(a23.x, b2, acc[2][2]);
            acc[2][3] = ffma2(a23.x, b3, acc[2][3]);
            acc[3][0] = ffma2(a23.y, b0, acc[3][0]);
            acc[3][1] = ffma2(a23.y, b1, acc[3][1]);
            acc[3][2] = ffma2(a23.y, b2, acc[3][2]);
            acc[3][3] = ffma2(a23.y, b3, acc[3][3]);
        }
    }

    float* base = g_projp + (size_t)blockIdx.y * Bq * Aq + a0 + tx * 4;
#pragma unroll
    for (int mi = 0; mi < 4; ++mi) {
        float4 r0, r1;
        unpack2(acc[mi][0], r0.x, r1.x);
        unpack2(acc[mi][1], r0.y, r1.y);
        unpack2(acc[mi][2], r0.z, r1.z);
        unpack2(acc[mi][3], r0.w, r1.w);
        const int m = ty * 8 + 2 * mi;
        *(float4*)(base + (size_t)m * Aq)       = r0;
        *(float4*)(base + (size_t)(m + 1) * Aq) = r1;
    }
}

// ---------------------------------------------------------------------------
// K2: g_proj = sum_z partials + bias.  Grid 128 x 256 thr, float4/thread.
// Partials are L2-resident (4MB).
// ---------------------------------------------------------------------------
__global__ void __launch_bounds__(256) k_reduce(const float* __restrict__ bsa) {
    const int idx = (blockIdx.x * 256 + threadIdx.x) * 4;
    const int a   = idx & (Aq - 1);
    float4 s = *(const float4*)(bsa + a);
#pragma unroll
    for (int z = 0; z < KSPLIT; ++z) {
        float4 p = *(const float4*)(g_projp + (size_t)z * Bq * Aq + idx);
        s.x += p.x;  s.y += p.y;  s.z += p.z;  s.w += p.w;
    }
    *(float4*)(g_proj + idx) = s;
}

// ---------------------------------------------------------------------------
// K3: score[l,b] = sum_a w_a1[a] * tanh(proj[b,a] + uh[l,b,a])
// One warp per (l,b); 8 warps share one b (proj + w_a1 staged in smem).
// Grid: B * L/8 = 2048 blocks, 256 threads.
// ---------------------------------------------------------------------------
__global__ void __launch_bounds__(256) k_scores(const float* __restrict__ uh,
                                                const float* __restrict__ w1) {
    const int b  = blockIdx.x >> 4;
    const int l0 = (blockIdx.x & 15) << 3;
    __shared__ float ps[Aq];
    __shared__ float ws[Aq];
    const int t  = threadIdx.x;
    const int i4 = t * 4;

    *(float4*)&ps[i4] = *(const float4*)(g_proj + (size_t)b * Aq + i4);
    *(float4*)&ws[i4] = *(const float4*)(w1 + i4);
    __syncthreads();

    const int w    = t >> 5;
    const int lane = t & 31;
    const int l    = l0 + w;
    const float* u = uh + (size_t)(l * Bq + b) * Aq;

    float acc = 0.f;
#pragma unroll
    for (int i = 0; i < 8; ++i) {
        int idx = i * 128 + lane * 4;
        float4 u4 = *(const float4*)(u + idx);
        float4 p4 = *(const float4*)&ps[idx];
        float4 w4 = *(const float4*)&ws[idx];
        acc = fmaf(w4.x, tanh_fast(p4.x + u4.x), acc);
        acc = fmaf(w4.y, tanh_fast(p4.y + u4.y), acc);
        acc = fmaf(w4.z, tanh_fast(p4.z + u4.z), acc);
        acc = fmaf(w4.w, tanh_fast(p4.w + u4.w), acc);
    }
#pragma unroll
    for (int off = 16; off; off >>= 1)
        acc += __shfl_xor_sync(0xffffffffu, acc, off);
    if (lane == 0) g_scores[l * Bq + b] = acc;
}

// ---------------------------------------------------------------------------
// K4: fused softmax + attend.
// Block = (b, 256-wide h chunk), 256 threads = 64 cols(x4) * 4 l-groups.
// Grid: B*8 = 1024 blocks -> ~56 warps/SM.
// ---------------------------------------------------------------------------
__global__ void __launch_bounds__(256) k_attend(const float* __restrict__ xs,
                                                const float* __restrict__ mask,
                                                const float* __restrict__ ba1,
                                                float* __restrict__ e_out,
                                                float* __restrict__ out) {
    const int b  = blockIdx.x >> 3;
    const int h0 = (blockIdx.x & 7) * 256;
    const int t  = threadIdx.x;

    __shared__ float  es[Lq];
    __shared__ float  red[4];
    __shared__ float4 pacc[256];

    // softmax over L (threads 0..127 hold one l each)
    float e = 0.f;
    if (t < 128)
        e = __expf(g_scores[t * Bq + b] + ba1[0]) * mask[t * Bq + b];
    float v = e;
#pragma unroll
    for (int off = 16; off; off >>= 1)
        v += __shfl_xor_sync(0xffffffffu, v, off);
    if (t < 128 && (t & 31) == 0) red[t >> 5] = v;
    __syncthreads();
    float s = red[0] + red[1] + red[2] + red[3];
    if (t < 128) es[t] = e / s;
    __syncthreads();
    if (h0 == 0 && t < 128) e_out[t * Bq + b] = es[t];

    // weighted sum over L: l-group g covers 32 l values
    const int col = t & 63;
    const int g   = t >> 6;
    const float* base = xs + (size_t)(g * 32) * Bq * Hq +
                        (size_t)b * Hq + h0 + col * 4;
    float4 acc = make_float4(0.f, 0.f, 0.f, 0.f);
#pragma unroll 8
    for (int i = 0; i < 32; ++i) {
        float4 vv = *(const float4*)(base + (size_t)i * Bq * Hq);
        float ev = es[g * 32 + i];
        acc.x = fmaf(ev, vv.x, acc.x);
        acc.y = fmaf(ev, vv.y, acc.y);
        acc.z = fmaf(ev, vv.z, acc.z);
        acc.w = fmaf(ev, vv.w, acc.w);
    }
    pacc[t] = acc;
    __syncthreads();
    if (g == 0) {
        float4 p1 = pacc[col + 64];
        float4 p2 = pacc[col + 128];
        float4 p3 = pacc[col + 192];
        acc.x += (p1.x + p2.x) + p3.x;
        acc.y += (p1.y + p2.y) + p3.y;
        acc.z += (p1.z + p2.z) + p3.z;
        acc.w += (p1.w + p2.w) + p3.w;
        *(float4*)(out + (size_t)b * Hq + h0 + col * 4) = acc;
    }
}

// ---------------------------------------------------------------------------
extern "C" void kernel_launch(void* const* d_in, const int* in_sizes, int n_in,
                              void* d_out, int out_size) {
    const float* s_tm1 = (const float*)d_in[0];
    const float* xs_h  = (const float*)d_in[1];
    const float* uh    = (const float*)d_in[2];
    const float* mask  = (const float*)d_in[3];
    const float* W_sa  = (const float*)d_in[4];
    const float* b_sa  = (const float*)d_in[5];
    const float* w_a1  = (const float*)d_in[6];
    const float* b_a1  = (const float*)d_in[7];
    float* out = (float*)d_out;  // [0 : L*B) = e_ij, [L*B : ) = attend

    k_proj<<<dim3(16, KSPLIT), 256>>>(s_tm1, W_sa);
    k_reduce<<<128, 256>>>(b_sa);
    k_scores<<<2048, 256>>>(uh, w_a1);
    k_attend<<<1024, 256>>>(xs_h, mask, b_a1, out, out + Lq * Bq);
}